// round 17
// baseline (speedup 1.0000x reference)
#include <cuda_runtime.h>
#include <cuda_fp16.h>
#include <cstdint>

#define NN 8192
#define FIN 512
#define FOUT 256
#define CH 32
#define CTA_M 64
#define JHALF (NN / 2)
#define NCH_H (JHALF / CH)      // 128 chunks per half
#define BSTRIDE 40              // smem stride (halves)
#define TILE_HALVES 8192        // one 32-j tile: 256 rows * 32 halves
#define TILE_BYTES 16384
#define ABUF_BYTES (CTA_M * BSTRIDE * 2)

// ---------------- scratch (device globals; no allocation allowed) -----------
__device__ __half  g_hT16[(size_t)FOUT * NN];
__device__ __half  g_W16T[(size_t)FOUT * FIN];
__device__ float   g_wl[FIN], g_wr[FIN];
__device__ float4  g_EFG[NN];                   // per-j: (E, F, G, 0)
__device__ float2  g_RT [NN];                   // per-i: (R=e^{-0.8f}, T=-f)
__device__ float   g_S[2][(size_t)NN * FOUT];
__device__ float   g_Z[2][NN];

// ---------------- helpers ----------------------------------------------------
static __device__ __forceinline__ uint32_t smem_u32(const void* p) {
    uint32_t a;
    asm("{ .reg .u64 t; cvta.to.shared.u64 t, %1; cvt.u32.u64 %0, t; }" : "=r"(a) : "l"(p));
    return a;
}
static __device__ __forceinline__ void cp16(uint32_t dst, const void* src) {
    asm volatile("cp.async.ca.shared.global [%0], [%1], 16;" :: "r"(dst), "l"(src));
}
static __device__ __forceinline__ void cp_commit() {
    asm volatile("cp.async.commit_group;");
}
static __device__ __forceinline__ void cp_wait_all() {
    asm volatile("cp.async.wait_group 0;");
}
static __device__ __forceinline__ void cp_wait1() {
    asm volatile("cp.async.wait_group 1;");
}
static __device__ __forceinline__ void ldsm4(uint32_t* r, uint32_t addr) {
    asm volatile("ldmatrix.sync.aligned.m8n8.x4.shared.b16 {%0,%1,%2,%3}, [%4];"
                 : "=r"(r[0]), "=r"(r[1]), "=r"(r[2]), "=r"(r[3]) : "r"(addr));
}
static __device__ __forceinline__ void mma16816(float* d, const uint32_t* a,
                                                uint32_t b0, uint32_t b1) {
    asm volatile(
        "mma.sync.aligned.m16n8k16.row.col.f32.f16.f16.f32 "
        "{%0,%1,%2,%3}, {%4,%5,%6,%7}, {%8,%9}, {%0,%1,%2,%3};"
        : "+f"(d[0]), "+f"(d[1]), "+f"(d[2]), "+f"(d[3])
        : "r"(a[0]), "r"(a[1]), "r"(a[2]), "r"(a[3]), "r"(b0), "r"(b1));
}

#define MBAR_INIT(addr, cnt) \
    asm volatile("mbarrier.init.shared.b64 [%0], %1;" :: "r"(addr), "r"(cnt) : "memory")
#define MBAR_EXPECT_TX(addr, tx) \
    asm volatile("mbarrier.arrive.expect_tx.shared.b64 _, [%0], %1;" :: "r"(addr), "r"(tx) : "memory")
#define MBAR_ARRIVE(addr) \
    asm volatile("mbarrier.arrive.shared.b64 _, [%0];" :: "r"(addr) : "memory")
#define CP_BULK(dst, src, bytes, mbar) \
    asm volatile("cp.async.bulk.shared::cta.global.mbarrier::complete_tx::bytes " \
                 "[%0], [%1], %2, [%3];" \
                 :: "r"(dst), "l"(src), "r"(bytes), "r"(mbar) : "memory")
#define MBAR_WAIT(addr, par) do {                                              \
    uint32_t _m = (addr), _p = (par), _d;                                      \
    asm volatile("{\n\t.reg .pred p;\n\t"                                      \
        "mbarrier.try_wait.parity.acquire.cta.shared::cta.b64 p, [%1], %2;\n\t"\
        "selp.b32 %0, 1, 0, p;\n\t}"                                           \
        : "=r"(_d) : "r"(_m), "r"(_p) : "memory");                             \
    if (!_d) {                                                                 \
        asm volatile("{\n\t.reg .pred P1;\n\t"                                 \
            "WL_%=:\n\t"                                                       \
            "mbarrier.try_wait.parity.acquire.cta.shared::cta.b64 P1, [%0], %1, 0x989680;\n\t" \
            "@P1 bra.uni WD_%=;\n\t"                                           \
            "bra.uni WL_%=;\n\t"                                               \
            "WD_%=:\n\t}" :: "r"(_m), "r"(_p) : "memory");                     \
    }                                                                          \
} while (0)
#define GROUP_BAR(grp) \
    asm volatile("bar.sync %0, %1;" :: "r"((grp) + 1), "r"(128) : "memory")

// ---------------------------------------------------------------------------
// Prep (FUSED): W -> fp16 transposed [n][k]  AND  wl/wr = W @ a halves.
// ---------------------------------------------------------------------------
__global__ void __launch_bounds__(256) k_prep(const float* __restrict__ W,
                                              const float* __restrict__ a) {
    const int tid = threadIdx.x;
#pragma unroll
    for (int r = 0; r < 8; r++) {
        const int k = blockIdx.x * 8 + r;
        g_W16T[(size_t)tid * FIN + k] = __float2half_rn(W[(size_t)k * FOUT + tid]);
    }
    const int wid  = tid >> 5;
    const int lane = tid & 31;
    const int k    = blockIdx.x * 8 + wid;
    float l = 0.f, r = 0.f;
#pragma unroll
    for (int q = 0; q < 8; q++) {
        const int c = q * 32 + lane;
        const float wv = W[(size_t)k * FOUT + c];
        l += wv * a[c];
        r += wv * a[FOUT + c];
    }
#pragma unroll
    for (int off = 16; off; off >>= 1) {
        l += __shfl_down_sync(0xffffffffu, l, off);
        r += __shfl_down_sync(0xffffffffu, r, off);
    }
    if (lane == 0) { g_wl[k] = l; g_wr[k] = r; }
}

// ---------------------------------------------------------------------------
// Scores directly from x (fp32 exact)
// ---------------------------------------------------------------------------
__global__ void __launch_bounds__(256) k_scores(const float* __restrict__ x) {
    const int wid  = threadIdx.x >> 5;
    const int lane = threadIdx.x & 31;
    const int i    = blockIdx.x * 8 + wid;

    float f = 0.f, g = 0.f;
#pragma unroll
    for (int q = 0; q < 4; q++) {
        const int k = q * 128 + lane * 4;
        float4 xv = *reinterpret_cast<const float4*>(&x[(size_t)i * FIN + k]);
        float4 lv = *reinterpret_cast<const float4*>(&g_wl[k]);
        float4 rv = *reinterpret_cast<const float4*>(&g_wr[k]);
        f += xv.x * lv.x + xv.y * lv.y + xv.z * lv.z + xv.w * lv.w;
        g += xv.x * rv.x + xv.y * rv.y + xv.z * rv.z + xv.w * rv.w;
    }
#pragma unroll
    for (int off = 16; off; off >>= 1) {
        f += __shfl_down_sync(0xffffffffu, f, off);
        g += __shfl_down_sync(0xffffffffu, g, off);
    }
    if (lane == 0) {
        g_EFG[i] = make_float4(expf(g), expf(0.2f * g), g, 0.f);
        g_RT[i]  = make_float2(expf(-0.8f * f), -f);
    }
}

// ---------------------------------------------------------------------------
// h = x @ W via fp16 mma; epilogue writes block-tiled PRE-SWIZZLED g_hT16.
// ---------------------------------------------------------------------------
#define XA_OFF 0
#define XB_OFF 10240
#define XD_OFF 10240
#define XW_SMEM 51200

__global__ void __launch_bounds__(256) k_xw_f16(const float* __restrict__ x) {
    extern __shared__ char smem[];
    const int tid  = threadIdx.x;
    const int lane = tid & 31;
    const int wid  = tid >> 5;
    const int wm   = wid >> 2;
    const int wn   = wid & 3;
    const int i0   = blockIdx.x * CTA_M;

    const int xr = tid >> 2;
    const int xk = (tid & 3) * 8;

    float acc[2][8][4];
#pragma unroll
    for (int mt = 0; mt < 2; mt++)
#pragma unroll
        for (int nt = 0; nt < 8; nt++)
#pragma unroll
            for (int q = 0; q < 4; q++) acc[mt][nt][q] = 0.f;

    const uint32_t sb = smem_u32(smem);
    const uint32_t aBase = sb + XA_OFF + ((wm * 32 + (lane & 15)) * BSTRIDE + (lane >> 4) * 8) * 2;
    const uint32_t bBase = sb + XB_OFF + ((wn * 64 + (lane & 15)) * BSTRIDE + (lane >> 4) * 8) * 2;

    float4 xa = *reinterpret_cast<const float4*>(&x[(size_t)(i0 + xr) * FIN + xk]);
    float4 xb = *reinterpret_cast<const float4*>(&x[(size_t)(i0 + xr) * FIN + xk + 4]);
    {
        uint32_t bdst = sb + XB_OFF + tid * (BSTRIDE * 2);
        const __half* bsrc = g_W16T + (size_t)tid * FIN;
#pragma unroll
        for (int q = 0; q < 4; q++) cp16(bdst + 16 * q, bsrc + 8 * q);
        cp_commit();
    }

    for (int c = 0; c < FIN / 32; c++) {
        const int cur = c & 1;
        cp_wait_all();
        __syncthreads();

        {
            __half2 hx[4];
            hx[0] = __floats2half2_rn(xa.x, xa.y);
            hx[1] = __floats2half2_rn(xa.z, xa.w);
            hx[2] = __floats2half2_rn(xb.x, xb.y);
            hx[3] = __floats2half2_rn(xb.z, xb.w);
            *reinterpret_cast<uint4*>(smem + XA_OFF + (cur * CTA_M * BSTRIDE + xr * BSTRIDE + xk) * 2) =
                *reinterpret_cast<uint4*>(hx);
        }
        if (c + 1 < FIN / 32) {
            const int k0 = (c + 1) * 32;
            xa = *reinterpret_cast<const float4*>(&x[(size_t)(i0 + xr) * FIN + k0 + xk]);
            xb = *reinterpret_cast<const float4*>(&x[(size_t)(i0 + xr) * FIN + k0 + xk + 4]);
            uint32_t bdst = sb + XB_OFF + ((cur ^ 1) * FOUT * BSTRIDE + tid * BSTRIDE) * 2;
            const __half* bsrc = g_W16T + (size_t)tid * FIN + k0;
#pragma unroll
            for (int q = 0; q < 4; q++) cp16(bdst + 16 * q, bsrc + 8 * q);
        }
        cp_commit();
        __syncthreads();

        const uint32_t aOff = cur * (uint32_t)(CTA_M * BSTRIDE * 2);
        const uint32_t bOff = cur * (uint32_t)(FOUT * BSTRIDE * 2);
#pragma unroll
        for (int ks = 0; ks < 2; ks++) {
            const uint32_t kOff = ks * 32;
            uint32_t af[2][4];
            ldsm4(af[0], aBase + aOff + kOff);
            ldsm4(af[1], aBase + aOff + kOff + 16 * BSTRIDE * 2);
            uint32_t bf[4][4];
#pragma unroll
            for (int np = 0; np < 4; np++)
                ldsm4(bf[np], bBase + bOff + kOff + np * 16 * BSTRIDE * 2);
#pragma unroll
            for (int np = 0; np < 4; np++) {
#pragma unroll
                for (int mt = 0; mt < 2; mt++) {
                    mma16816(acc[mt][2 * np],     af[mt], bf[np][0], bf[np][2]);
                    mma16816(acc[mt][2 * np + 1], af[mt], bf[np][1], bf[np][3]);
                }
            }
        }
        __syncthreads();
    }

    __half* Dp = reinterpret_cast<__half*>(smem + XD_OFF);   // [64][264]
#pragma unroll
    for (int mt = 0; mt < 2; mt++) {
        const int rca = wm * 32 + mt * 16 + (lane >> 2);
        const int c0  = wn * 64 + 2 * (lane & 3);
#pragma unroll
        for (int nt = 0; nt < 8; nt++) {
            const int cc = c0 + nt * 8;
            *reinterpret_cast<__half2*>(&Dp[rca * 264 + cc]) =
                __floats2half2_rn(acc[mt][nt][0], acc[mt][nt][1]);
            *reinterpret_cast<__half2*>(&Dp[(rca + 8) * 264 + cc]) =
                __floats2half2_rn(acc[mt][nt][2], acc[mt][nt][3]);
        }
    }
    __syncthreads();

    const int ib0 = blockIdx.x * 2;
    const int m   = (tid >> 1) & 3;
#pragma unroll
    for (int blk = 0; blk < 2; blk++) {
        __half* dst = g_hT16 + (size_t)(ib0 + blk) * TILE_HALVES + tid * 32;
#pragma unroll
        for (int u = 0; u < 4; u++) {
            __half2 v[4];
#pragma unroll
            for (int w = 0; w < 4; w++)
                v[w] = __halves2half2(Dp[(blk * 32 + u * 8 + 2 * w) * 264 + tid],
                                      Dp[(blk * 32 + u * 8 + 2 * w + 1) * 264 + tid]);
            *reinterpret_cast<uint4*>(dst + ((u ^ m) << 3)) = *reinterpret_cast<uint4*>(v);
        }
    }
}

// ---------------------------------------------------------------------------
// Attention: R16 group-desync structure; EFG now staged in a per-group
// 4-deep smem ring via cp.async (issued 3 chunks ahead), read via LDS.
// ---------------------------------------------------------------------------
__global__ void __launch_bounds__(256, 2) k_attn_f16(const int* __restrict__ adj) {
    __shared__ __align__(16)  __half A_s[2][CTA_M][BSTRIDE];
    __shared__ __align__(128) __half B_s[2][TILE_HALVES];
    __shared__ __align__(16)  float4 EFG_s[2][4][CH];    // [group][slot][j]
    __shared__ float zs[256];
    __shared__ __align__(8) unsigned long long mbar[4];  // full0 full1 empty0 empty1

    const int tid  = threadIdx.x;
    const int lane = tid & 31;
    const int wid  = tid >> 5;
    const int wm   = wid >> 2;          // group id
    const int wn   = wid & 3;
    const int rb   = blockIdx.x >> 1;
    const int half = blockIdx.x & 1;
    const int i0   = rb * CTA_M;
    const int jb   = half * JHALF;
    const int jblk0 = jb >> 5;

    const int pr = tid >> 2;            // P-gen row (group-local)
    const int kq = (tid & 3) * 8;
    const int stager = ((tid & 127) < 32);
    const int sl = tid & 31;            // stager lane

    const float2 rt = g_RT[i0 + pr];
    const float Ri = rt.x, Ti = rt.y;
    float zacc = 0.f;

    float acc[2][8][4];
#pragma unroll
    for (int mt = 0; mt < 2; mt++)
#pragma unroll
        for (int nt = 0; nt < 8; nt++)
#pragma unroll
            for (int q = 0; q < 4; q++) acc[mt][nt][q] = 0.f;

    const uint32_t aAddrBase = smem_u32(&A_s[0][wm * 32 + (lane & 15)][(lane >> 4) * 8]);
    const uint32_t bTile0    = smem_u32(&B_s[0][0]);
    const uint32_t mbF       = smem_u32(&mbar[0]);
    const uint32_t mbE       = smem_u32(&mbar[2]);

    uint32_t bRowOff[4], bM[4];
#pragma unroll
    for (int np = 0; np < 4; np++) {
        const int r = wn * 64 + np * 16 + (lane & 15);
        bRowOff[np] = (uint32_t)r * 64u;
        bM[np] = (uint32_t)((r >> 1) & 3);
    }
    const uint32_t cHi = (uint32_t)(lane >> 4);

    if (tid == 0) {
        MBAR_INIT(mbF,     1u);
        MBAR_INIT(mbF + 8, 1u);
        MBAR_INIT(mbE,     2u);
        MBAR_INIT(mbE + 8, 2u);
    }
    __syncthreads();

    // prologue: bulk B chunk 0; stage EFG chunks 0..2; P-gen chunk 0 into A[0]
    if (tid == 0) {
        MBAR_EXPECT_TX(mbF, 16384u);
        CP_BULK(bTile0, (const char*)(g_hT16 + (size_t)jblk0 * TILE_HALVES), 16384u, mbF);
    }
    if (stager) {
#pragma unroll
        for (int s = 0; s < 3; s++) {
            cp16(smem_u32(&EFG_s[wm][s][sl]), g_EFG + jb + s * CH + sl);
            cp_commit();
        }
        cp_wait1();       // e0, e1 complete (e2 may be in flight)
    }
    GROUP_BAR(wm);        // EFG[0..1] visible to group

    const int4* arow = reinterpret_cast<const int4*>(adj + (size_t)(i0 + pr) * NN + jb);
    {
        int4 a0 = arow[kq >> 2];
        int4 a1 = arow[(kq >> 2) + 1];
        const float4* eb = EFG_s[wm][0];
        int avv[8] = {a0.x, a0.y, a0.z, a0.w, a1.x, a1.y, a1.z, a1.w};
        __half2 hp[4];
#pragma unroll
        for (int u = 0; u < 8; u += 2) {
            float4 e0 = eb[kq + u];
            float4 e1 = eb[kq + u + 1];
            float p0 = (e0.z > Ti) ? e0.x : Ri * e0.y;
            float p1 = (e1.z > Ti) ? e1.x : Ri * e1.y;
            p0 = (avv[u] > 0) ? p0 : 0.f;
            p1 = (avv[u + 1] > 0) ? p1 : 0.f;
            zacc += p0 + p1;
            hp[u >> 1] = __floats2half2_rn(p0, p1);
        }
        *reinterpret_cast<uint4*>(&A_s[0][pr][kq]) = *reinterpret_cast<uint4*>(hp);
    }
    GROUP_BAR(wm);   // publish A[0] within group

    for (int c = 0; c < NCH_H; c++) {
        const int cur = c & 1, nxt = cur ^ 1;

        // B producer: issue bulk for chunk c+1 into stage nxt
        if (tid == 0 && c + 1 < NCH_H) {
            const int k = c + 1;
            const uint32_t mbn = mbF + 8u * (uint32_t)nxt;
            if (k >= 2) MBAR_WAIT(mbE + 8u * (uint32_t)(k & 1), ((k >> 1) & 1) ^ 1);
            MBAR_EXPECT_TX(mbn, 16384u);
            CP_BULK(bTile0 + (uint32_t)nxt * TILE_BYTES,
                    (const char*)(g_hT16 + (size_t)(jblk0 + c + 1) * TILE_HALVES), 16384u, mbn);
        }
        // EFG stager: issue chunk c+3 into slot (c+3)&3
        if (stager && c + 3 < NCH_H) {
            const int s = (c + 3) & 3;
            cp16(smem_u32(&EFG_s[wm][s][sl]), g_EFG + jb + (c + 3) * CH + sl);
            cp_commit();
        }
        int4 a0, a1;
        if (c + 1 < NCH_H) {
            const int ji = ((c + 1) * CH + kq) >> 2;
            a0 = arow[ji];
            a1 = arow[ji + 1];
        }

        MBAR_WAIT(mbF + 8u * (uint32_t)cur, (c >> 1) & 1);   // chunk c's B tile

        // ---- mma on chunk c ----
        const uint32_t aBufBase = aAddrBase + (uint32_t)cur * ABUF_BYTES;
        const uint32_t bBufBase = bTile0 + (uint32_t)cur * TILE_BYTES;
#pragma unroll
        for (int ks = 0; ks < 2; ks++) {
            const uint32_t kOff = ks * 32;
            uint32_t af[2][4];
            ldsm4(af[0], aBufBase + kOff);
            ldsm4(af[1], aBufBase + kOff + 16 * BSTRIDE * 2);
            const uint32_t c16 = cHi + 2u * (uint32_t)ks;
            uint32_t bf[4][4];
#pragma unroll
            for (int np = 0; np < 4; np++)
                ldsm4(bf[np], bBufBase + bRowOff[np] + (((c16 ^ bM[np])) << 4));
#pragma unroll
            for (int np = 0; np < 4; np++) {
#pragma unroll
                for (int mt = 0; mt < 2; mt++) {
                    mma16816(acc[mt][2 * np],     af[mt], bf[np][0], bf[np][2]);
                    mma16816(acc[mt][2 * np + 1], af[mt], bf[np][1], bf[np][3]);
                }
            }
        }

        // ---- P-gen chunk c+1 into A[nxt] (EFG via smem ring) ----
        if (c + 1 < NCH_H) {
            const float4* eb = EFG_s[wm][(c + 1) & 3];
            int avv[8] = {a0.x, a0.y, a0.z, a0.w, a1.x, a1.y, a1.z, a1.w};
            __half2 hp[4];
#pragma unroll
            for (int u = 0; u < 8; u += 2) {
                float4 e0 = eb[kq + u];
                float4 e1 = eb[kq + u + 1];
                float p0 = (e0.z > Ti) ? e0.x : Ri * e0.y;
                float p1 = (e1.z > Ti) ? e1.x : Ri * e1.y;
                p0 = (avv[u] > 0) ? p0 : 0.f;
                p1 = (avv[u + 1] > 0) ? p1 : 0.f;
                zacc += p0 + p1;
                hp[u >> 1] = __floats2half2_rn(p0, p1);
            }
            *reinterpret_cast<uint4*>(&A_s[nxt][pr][kq]) = *reinterpret_cast<uint4*>(hp);
        }

        // stager drains EFG copies needed next iteration, then group converges
        if (stager) {
            if (c + 3 < NCH_H) cp_wait1();
            else               cp_wait_all();
        }
        GROUP_BAR(wm);   // A[nxt] + EFG slot published; B[cur]/A[cur] reads done
        if ((tid & 127) == 0)
            MBAR_ARRIVE(mbE + 8u * (uint32_t)cur);   // group signals B[cur] free
    }

    // ---- converge both groups, then row sums + store ----
    zs[tid] = zacc;
    __syncthreads();
    if (tid < CTA_M)
        g_Z[half][i0 + tid] = zs[4 * tid] + zs[4 * tid + 1] + zs[4 * tid + 2] + zs[4 * tid + 3];

    float* Sp = g_S[half];
#pragma unroll
    for (int mt = 0; mt < 2; mt++) {
        const int rca = wm * 32 + mt * 16 + (lane >> 2);
        float* o0 = Sp + (size_t)(i0 + rca) * FOUT;
        float* o1 = Sp + (size_t)(i0 + rca + 8) * FOUT;
#pragma unroll
        for (int nt = 0; nt < 8; nt++) {
            const int colb = wn * 64 + nt * 8 + 2 * (lane & 3);
            *reinterpret_cast<float2*>(o0 + colb) = make_float2(acc[mt][nt][0], acc[mt][nt][1]);
            *reinterpret_cast<float2*>(o1 + colb) = make_float2(acc[mt][nt][2], acc[mt][nt][3]);
        }
    }
}

// ---------------------------------------------------------------------------
// Combine halves (vectorized): out = (S0+S1) / (Z0+Z1)
// ---------------------------------------------------------------------------
__global__ void __launch_bounds__(256) k_combine(float* __restrict__ out) {
    const int t   = threadIdx.x;
    const int i   = blockIdx.x * 4 + (t >> 6);
    const int c4  = (t & 63) * 4;
    const float inv = 1.0f / (g_Z[0][i] + g_Z[1][i]);
    const size_t idx = (size_t)i * FOUT + c4;
    float4 s0 = *reinterpret_cast<const float4*>(&g_S[0][idx]);
    float4 s1 = *reinterpret_cast<const float4*>(&g_S[1][idx]);
    *reinterpret_cast<float4*>(&out[idx]) =
        make_float4((s0.x + s1.x) * inv, (s0.y + s1.y) * inv,
                    (s0.z + s1.z) * inv, (s0.w + s1.w) * inv);
}

// ---------------------------------------------------------------------------
extern "C" void kernel_launch(void* const* d_in, const int* in_sizes, int n_in,
                              void* d_out, int out_size) {
    const float* x   = (const float*)d_in[0];
    const int*   adj = (const int*)  d_in[1];
    const float* W   = (const float*)d_in[2];
    const float* a   = (const float*)d_in[3];
    float* out = (float*)d_out;

    cudaFuncSetAttribute(k_xw_f16, cudaFuncAttributeMaxDynamicSharedMemorySize, XW_SMEM);

    k_prep<<<FIN / 8, 256>>>(W, a);                 // launch 0
    k_xw_f16<<<NN / CTA_M, 256, XW_SMEM>>>(x);      // launch 1
    k_scores<<<NN / 8, 256>>>(x);                   // launch 2
    k_attn_f16<<<(NN / CTA_M) * 2, 256>>>(adj);     // launch 3  <- ncu capture
    k_combine<<<NN / 4, 256>>>(out);                // launch 4
}